// round 1
// baseline (speedup 1.0000x reference)
#include <cuda_runtime.h>

// Problem constants
static constexpr int B_   = 8;
static constexpr int C_   = 256;
static constexpr int CQK_ = 32;
static constexpr int N_   = 4096;   // 64*64 spatial

// Scratch (static __device__ arrays: allocation-free per harness rules)
__device__ float g_q[(size_t)B_ * CQK_ * N_];   // 4 MB
__device__ float g_k[(size_t)B_ * CQK_ * N_];   // 4 MB
__device__ float g_v[(size_t)B_ * C_   * N_];   // 32 MB
__device__ float g_o[(size_t)B_ * C_   * N_];   // 32 MB

// ---------------------------------------------------------------------------
// Projection: Y[b,m,n] = sum_c W[m,c] * X[b,c,n] + bias[m]
// W: [O, 256] row-major, X: [B, 256, N], Y: [B, O, N]
// BM in {32, 64}; block = 256 threads; BN = 64, BK = 32.
// ---------------------------------------------------------------------------
template <int BM>
__global__ __launch_bounds__(256)
void proj_kernel(const float* __restrict__ W, const float* __restrict__ bias,
                 const float* __restrict__ X, float* __restrict__ Y, int O)
{
    constexpr int BK = 32;
    constexpr int BN = 64;
    constexpr int TM = BM / 16;   // 4 for BM=64, 2 for BM=32
    constexpr int TN = 4;

    __shared__ float Ws[BK][BM + 1];  // +1 pad: conflict-free k-inner writes
    __shared__ float Xs[BK][BN];

    const int b  = blockIdx.z;
    const int m0 = blockIdx.y * BM;
    const int n0 = blockIdx.x * BN;

    const float* Xb = X + (size_t)b * C_ * N_;
    float*       Yb = Y + (size_t)b * O  * N_;

    const int tid = threadIdx.x;
    const int tm  = (tid / 16) * TM;
    const int tn  = (tid % 16) * TN;

    float acc[TM][TN];
#pragma unroll
    for (int i = 0; i < TM; i++)
#pragma unroll
        for (int j = 0; j < TN; j++) acc[i][j] = 0.f;

    for (int k0 = 0; k0 < C_; k0 += BK) {
        // W tile: BM x BK, k-inner => coalesced 128B rows
        for (int i = tid; i < BM * BK; i += 256) {
            int m = i / BK, k = i % BK;
            Ws[k][m] = W[(size_t)(m0 + m) * C_ + (k0 + k)];
        }
        // X tile: BK x BN, n-inner => coalesced
        for (int i = tid; i < BK * BN; i += 256) {
            int k = i / BN, n = i % BN;
            Xs[k][n] = Xb[(size_t)(k0 + k) * N_ + (n0 + n)];
        }
        __syncthreads();

#pragma unroll
        for (int k = 0; k < BK; k++) {
            float wr[TM], xr[TN];
#pragma unroll
            for (int i = 0; i < TM; i++) wr[i] = Ws[k][tm + i];
#pragma unroll
            for (int j = 0; j < TN; j++) xr[j] = Xs[k][tn + j];
#pragma unroll
            for (int i = 0; i < TM; i++)
#pragma unroll
                for (int j = 0; j < TN; j++)
                    acc[i][j] += wr[i] * xr[j];
        }
        __syncthreads();
    }

#pragma unroll
    for (int i = 0; i < TM; i++) {
        float bb = bias[m0 + tm + i];
#pragma unroll
        for (int j = 0; j < TN; j++)
            Yb[(size_t)(m0 + tm + i) * N_ + (n0 + tn + j)] = acc[i][j] + bb;
    }
}

// ---------------------------------------------------------------------------
// Flash attention (fp32):
//   Q,K: [B, 32, N]; V: [B, 256, N]; O: [B, 256, N]
//   Per CTA: one batch, 64 queries. Stream 64-key tiles with online softmax.
//   Thread (256): cgrp = tid/8 -> 8 channels, qgrp = tid%8 -> 8 queries;
//   acc[8][8] in registers.
// ---------------------------------------------------------------------------
static constexpr int FL_SMEM_FLOATS =
    32 * 64      /* Qs */ +
    32 * 64      /* Ks */ +
    64 * 65      /* Ps (padded) */ +
    256 * 65     /* Vs (padded) */ +
    64 * 3       /* sm, sl, sa */;
static constexpr int FL_SMEM_BYTES = FL_SMEM_FLOATS * 4;  // 100,928 B

__global__ __launch_bounds__(256, 2)
void flash_kernel(const float* __restrict__ Q, const float* __restrict__ K,
                  const float* __restrict__ V, float* __restrict__ O)
{
    extern __shared__ float sh[];
    float* Qs = sh;                    // [32][64]
    float* Ks = Qs + 32 * 64;          // [32][64]
    float* Ps = Ks + 32 * 64;          // [64][65]
    float* Vs = Ps + 64 * 65;          // [256][65]
    float* sm = Vs + 256 * 65;         // [64] running max
    float* sl = sm + 64;               // [64] running denom
    float* sa = sl + 64;               // [64] alpha

    const int tid = threadIdx.x;
    const int b   = blockIdx.y;
    const int q0  = blockIdx.x * 64;

    const float* Qb = Q + (size_t)b * CQK_ * N_;
    const float* Kb = K + (size_t)b * CQK_ * N_;
    const float* Vb = V + (size_t)b * C_   * N_;

    // PV mapping
    const int c0t = (tid >> 3) * 8;    // 8 channels
    const int q0t = (tid & 7)  * 8;    // 8 queries
    // S mapping (4x4 micro-tile of 64x64)
    const int si0 = (tid >> 4) * 4;
    const int sj0 = (tid & 15) * 4;

    // Load Q tile [32][64] (float4, coalesced: q0 is 64-aligned)
    for (int i = tid; i < 512; i += 256) {
        int c = i >> 4, j4 = (i & 15) * 4;
        float4 v4 = *(const float4*)&Qb[(size_t)c * N_ + q0 + j4];
        Qs[c * 64 + j4 + 0] = v4.x; Qs[c * 64 + j4 + 1] = v4.y;
        Qs[c * 64 + j4 + 2] = v4.z; Qs[c * 64 + j4 + 3] = v4.w;
    }
    if (tid < 64) { sm[tid] = -1e30f; sl[tid] = 0.f; }

    float acc[8][8];
#pragma unroll
    for (int i = 0; i < 8; i++)
#pragma unroll
        for (int j = 0; j < 8; j++) acc[i][j] = 0.f;

    for (int kt = 0; kt < N_ / 64; kt++) {
        const int j0 = kt * 64;

        // K tile [32][64]
        for (int i = tid; i < 512; i += 256) {
            int c = i >> 4, j4 = (i & 15) * 4;
            float4 v4 = *(const float4*)&Kb[(size_t)c * N_ + j0 + j4];
            Ks[c * 64 + j4 + 0] = v4.x; Ks[c * 64 + j4 + 1] = v4.y;
            Ks[c * 64 + j4 + 2] = v4.z; Ks[c * 64 + j4 + 3] = v4.w;
        }
        // V tile [256][64] -> Vs stride 65 (conflict-free reads)
        for (int i = tid; i < 4096; i += 256) {
            int c = i >> 4, j4 = (i & 15) * 4;
            float4 v4 = *(const float4*)&Vb[(size_t)c * N_ + j0 + j4];
            Vs[c * 65 + j4 + 0] = v4.x; Vs[c * 65 + j4 + 1] = v4.y;
            Vs[c * 65 + j4 + 2] = v4.z; Vs[c * 65 + j4 + 3] = v4.w;
        }
        __syncthreads();

        // S[i][j] = sum_c Q[c][i] * K[c][j]
        float s[4][4];
#pragma unroll
        for (int i = 0; i < 4; i++)
#pragma unroll
            for (int j = 0; j < 4; j++) s[i][j] = 0.f;
#pragma unroll
        for (int c = 0; c < 32; c++) {
            float qr[4], kr[4];
#pragma unroll
            for (int i = 0; i < 4; i++) qr[i] = Qs[c * 64 + si0 + i];
#pragma unroll
            for (int j = 0; j < 4; j++) kr[j] = Ks[c * 64 + sj0 + j];
#pragma unroll
            for (int i = 0; i < 4; i++)
#pragma unroll
                for (int j = 0; j < 4; j++) s[i][j] += qr[i] * kr[j];
        }
#pragma unroll
        for (int i = 0; i < 4; i++)
#pragma unroll
            for (int j = 0; j < 4; j++)
                Ps[(si0 + i) * 65 + sj0 + j] = s[i][j];
        __syncthreads();

        // Row max + alpha (threads 0..63, one per query row)
        if (tid < 64) {
            float mx = -1e30f;
#pragma unroll 8
            for (int j = 0; j < 64; j++) mx = fmaxf(mx, Ps[tid * 65 + j]);
            float mold = sm[tid];
            float mnew = fmaxf(mold, mx);
            sa[tid] = __expf(mold - mnew);
            sm[tid] = mnew;
        }
        __syncthreads();

        // P = exp(S - m_new), written from register copy of S
#pragma unroll
        for (int i = 0; i < 4; i++) {
            float mrow = sm[si0 + i];
#pragma unroll
            for (int j = 0; j < 4; j++)
                Ps[(si0 + i) * 65 + sj0 + j] = __expf(s[i][j] - mrow);
        }
        __syncthreads();

        // l update (threads 0..63) — concurrent with PV, no data hazard
        if (tid < 64) {
            float sum = 0.f;
#pragma unroll 8
            for (int j = 0; j < 64; j++) sum += Ps[tid * 65 + j];
            sl[tid] = sl[tid] * sa[tid] + sum;
        }

        // PV accumulate with alpha rescale
        float al[8];
#pragma unroll
        for (int qq = 0; qq < 8; qq++) al[qq] = sa[q0t + qq];
#pragma unroll
        for (int cc = 0; cc < 8; cc++)
#pragma unroll
            for (int qq = 0; qq < 8; qq++) acc[cc][qq] *= al[qq];

#pragma unroll 4
        for (int j = 0; j < 64; j++) {
            float pv[8];
#pragma unroll
            for (int qq = 0; qq < 8; qq++) pv[qq] = Ps[(q0t + qq) * 65 + j];
#pragma unroll
            for (int cc = 0; cc < 8; cc++) {
                float vv = Vs[(c0t + cc) * 65 + j];
#pragma unroll
                for (int qq = 0; qq < 8; qq++) acc[cc][qq] += vv * pv[qq];
            }
        }
        __syncthreads();  // protect Ks/Vs/Ps for next tile; also orders sl
    }

    // Normalize and store
    float rl[8];
#pragma unroll
    for (int qq = 0; qq < 8; qq++) rl[qq] = 1.f / sl[q0t + qq];

    float* Ob = O + (size_t)b * C_ * N_;
#pragma unroll
    for (int cc = 0; cc < 8; cc++) {
#pragma unroll
        for (int qq = 0; qq < 8; qq++) {
            Ob[(size_t)(c0t + cc) * N_ + q0 + q0t + qq] = acc[cc][qq] * rl[qq];
        }
    }
}

// ---------------------------------------------------------------------------
// kernel_launch
// Inputs (metadata order): x, Wq, bq, Wk, bk, Wv, bv, Wf, bf
// Output: float32 [B, C, H, W] = [8, 256, 64, 64]
// ---------------------------------------------------------------------------
extern "C" void kernel_launch(void* const* d_in, const int* in_sizes, int n_in,
                              void* d_out, int out_size)
{
    (void)in_sizes; (void)n_in; (void)out_size;
    const float* x  = (const float*)d_in[0];
    const float* Wq = (const float*)d_in[1];
    const float* bq = (const float*)d_in[2];
    const float* Wk = (const float*)d_in[3];
    const float* bk = (const float*)d_in[4];
    const float* Wv = (const float*)d_in[5];
    const float* bv = (const float*)d_in[6];
    const float* Wf = (const float*)d_in[7];
    const float* bf = (const float*)d_in[8];
    float* out = (float*)d_out;

    float *gq, *gk, *gv, *go;
    cudaGetSymbolAddress((void**)&gq, g_q);
    cudaGetSymbolAddress((void**)&gk, g_k);
    cudaGetSymbolAddress((void**)&gv, g_v);
    cudaGetSymbolAddress((void**)&go, g_o);

    cudaFuncSetAttribute(flash_kernel,
                         cudaFuncAttributeMaxDynamicSharedMemorySize,
                         FL_SMEM_BYTES);

    // Q, K projections: O=32
    proj_kernel<32><<<dim3(N_ / 64, 1, B_), 256>>>(Wq, bq, x, gq, CQK_);
    proj_kernel<32><<<dim3(N_ / 64, 1, B_), 256>>>(Wk, bk, x, gk, CQK_);
    // V projection: O=256
    proj_kernel<64><<<dim3(N_ / 64, C_ / 64, B_), 256>>>(Wv, bv, x, gv, C_);
    // Flash attention
    flash_kernel<<<dim3(N_ / 64, B_), 256, FL_SMEM_BYTES>>>(gq, gk, gv, go);
    // Final projection: O=256, input = attention output
    proj_kernel<64><<<dim3(N_ / 64, C_ / 64, B_), 256>>>(Wf, bf, go, out, C_);
}

// round 2
// speedup vs baseline: 1.2283x; 1.2283x over previous
#include <cuda_runtime.h>

// Problem constants
static constexpr int B_   = 8;
static constexpr int C_   = 256;
static constexpr int CQK_ = 32;
static constexpr int N_   = 4096;   // 64*64 spatial

// Scratch (static __device__ arrays: allocation-free per harness rules)
__device__ float g_q[(size_t)B_ * CQK_ * N_];   // 4 MB
__device__ float g_k[(size_t)B_ * CQK_ * N_];   // 4 MB
__device__ float g_v[(size_t)B_ * C_   * N_];   // 32 MB
__device__ float g_o[(size_t)B_ * C_   * N_];   // 32 MB

// ---------------------------------------------------------------------------
// Packed f32x2 helpers (sm_103a FFMA2 path — PTX only)
// ---------------------------------------------------------------------------
using u64_t = unsigned long long;

__device__ __forceinline__ u64_t pack2(float lo, float hi) {
    u64_t r;
    asm("mov.b64 %0, {%1, %2};" : "=l"(r) : "f"(lo), "f"(hi));
    return r;
}
__device__ __forceinline__ u64_t bcast2(float x) { return pack2(x, x); }
__device__ __forceinline__ u64_t fma2(u64_t a, u64_t b, u64_t c) {
    u64_t d;
    asm("fma.rn.f32x2 %0, %1, %2, %3;" : "=l"(d) : "l"(a), "l"(b), "l"(c));
    return d;
}
__device__ __forceinline__ u64_t mul2(u64_t a, u64_t b) {
    u64_t d;
    asm("mul.rn.f32x2 %0, %1, %2;" : "=l"(d) : "l"(a), "l"(b));
    return d;
}
__device__ __forceinline__ float2 unpack2(u64_t a) {
    float2 f;
    asm("mov.b64 {%0, %1}, %2;" : "=f"(f.x), "=f"(f.y) : "l"(a));
    return f;
}

// ---------------------------------------------------------------------------
// Projection: Y[b,m,n] = sum_c W[m,c] * X[b,c,n] + bias[m]
// W: [O, 256] row-major, X: [B, 256, N], Y: [B, O, N]
// BM in {32, 64}; block = 256 threads; BN = 64, BK = 32. Packed f32x2 inner.
// ---------------------------------------------------------------------------
template <int BM>
__global__ __launch_bounds__(256)
void proj_kernel(const float* __restrict__ W, const float* __restrict__ bias,
                 const float* __restrict__ X, float* __restrict__ Y, int O)
{
    constexpr int BK = 32;
    constexpr int BN = 64;
    constexpr int TM = BM / 16;   // 4 for BM=64, 2 for BM=32
    constexpr int TN = 4;

    __shared__ float Ws[BK][BM + 4];  // +4 pad: keeps rows 16B-aligned
    __shared__ float Xs[BK][BN];

    const int b  = blockIdx.z;
    const int m0 = blockIdx.y * BM;
    const int n0 = blockIdx.x * BN;

    const float* Xb = X + (size_t)b * C_ * N_;
    float*       Yb = Y + (size_t)b * O  * N_;

    const int tid = threadIdx.x;
    const int tm  = (tid / 16) * TM;
    const int tn  = (tid % 16) * TN;

    u64_t acc2[TM][TN / 2];
#pragma unroll
    for (int i = 0; i < TM; i++)
#pragma unroll
        for (int j = 0; j < TN / 2; j++) acc2[i][j] = pack2(0.f, 0.f);

    for (int k0 = 0; k0 < C_; k0 += BK) {
        // W tile: BM x BK, k-inner => coalesced 128B rows
        for (int i = tid; i < BM * BK; i += 256) {
            int m = i / BK, k = i % BK;
            Ws[k][m] = W[(size_t)(m0 + m) * C_ + (k0 + k)];
        }
        // X tile: BK x BN, n-inner => coalesced
        for (int i = tid; i < BK * BN / 4; i += 256) {
            int k = i / (BN / 4), n4 = (i % (BN / 4)) * 4;
            *(float4*)&Xs[k][n4] = *(const float4*)&Xb[(size_t)(k0 + k) * N_ + (n0 + n4)];
        }
        __syncthreads();

#pragma unroll
        for (int k = 0; k < BK; k++) {
            float wr[TM];
            if constexpr (TM == 4) {
                float4 w4 = *(const float4*)&Ws[k][tm];
                wr[0] = w4.x; wr[1] = w4.y; wr[2] = w4.z; wr[3] = w4.w;
            } else {
                float2 w2 = *(const float2*)&Ws[k][tm];
                wr[0] = w2.x; wr[1] = w2.y;
            }
            float4 x4 = *(const float4*)&Xs[k][tn];
            u64_t xp0 = pack2(x4.x, x4.y);
            u64_t xp1 = pack2(x4.z, x4.w);
#pragma unroll
            for (int i = 0; i < TM; i++) {
                u64_t wb = bcast2(wr[i]);
                acc2[i][0] = fma2(xp0, wb, acc2[i][0]);
                acc2[i][1] = fma2(xp1, wb, acc2[i][1]);
            }
        }
        __syncthreads();
    }

#pragma unroll
    for (int i = 0; i < TM; i++) {
        float bb = bias[m0 + tm + i];
        float2 a0 = unpack2(acc2[i][0]);
        float2 a1 = unpack2(acc2[i][1]);
        float4 o4 = make_float4(a0.x + bb, a0.y + bb, a1.x + bb, a1.y + bb);
        *(float4*)&Yb[(size_t)(m0 + tm + i) * N_ + (n0 + tn)] = o4;
    }
}

// ---------------------------------------------------------------------------
// Flash attention (fp32, packed f32x2 math):
//   Q,K: [B, 32, N]; V: [B, 256, N]; O: [B, 256, N]
//   Per CTA: one batch, 64 queries. Stream 64-key tiles with online softmax.
//   P and V tiles stored j-major with XOR swizzle for LDS.128 reads.
//   Thread: 8 channels x 8 queries in packed accumulators.
// ---------------------------------------------------------------------------
static constexpr int FL_SMEM_FLOATS =
    32 * 64      /* Qs [c][q]           */ +
    32 * 64      /* Ks [c][j]           */ +
    64 * 64      /* Ps [j][q] swizzled  */ +
    64 * 256     /* Vs [j][c] swizzled  */ +
    64 * 3       /* smax, ssum, salpha  */;
static constexpr int FL_SMEM_BYTES = FL_SMEM_FLOATS * 4;  // 99,072 B

__global__ __launch_bounds__(256, 2)
void flash_kernel(const float* __restrict__ Q, const float* __restrict__ K,
                  const float* __restrict__ V, float* __restrict__ O)
{
    extern __shared__ float sh[];
    float* Qs     = sh;                 // [32][64]
    float* Ks     = Qs + 32 * 64;       // [32][64]
    float* Ps     = Ks + 32 * 64;       // [64][64]  j-major, swizzled
    float* Vs     = Ps + 64 * 64;       // [64][256] j-major, swizzled
    float* smax   = Vs + 64 * 256;      // [64]
    float* ssum   = smax + 64;          // [64]
    float* salpha = ssum + 64;          // [64]

    const int tid = threadIdx.x;
    const int b   = blockIdx.y;
    const int q0  = blockIdx.x * 64;

    const float* Qb = Q + (size_t)b * CQK_ * N_;
    const float* Kb = K + (size_t)b * CQK_ * N_;
    const float* Vb = V + (size_t)b * C_   * N_;

    // PV mapping: 8 queries (contiguous) x 8 channels (contiguous)
    const int q0t = (tid & 7)  * 8;
    const int c0t = (tid >> 3) * 8;
    // S mapping: 4 queries x 4 keys micro-tile of the 64x64 score tile.
    // Row group = 16 lanes sharing si0 (same half-warp) -> shfl reductions.
    const int si0 = (tid >> 4) * 4;
    const int sj0 = (tid & 15) * 4;

    // Load Q tile [32][64]
    for (int i = tid; i < 512; i += 256) {
        int c = i >> 4, j4 = (i & 15) * 4;
        *(float4*)&Qs[c * 64 + j4] = *(const float4*)&Qb[(size_t)c * N_ + q0 + j4];
    }
    if (tid < 64) { smax[tid] = -1e30f; ssum[tid] = 0.f; }

    u64_t acc2[8][4];  // [qq][cc pair]
#pragma unroll
    for (int i = 0; i < 8; i++)
#pragma unroll
        for (int j = 0; j < 4; j++) acc2[i][j] = pack2(0.f, 0.f);

    for (int kt = 0; kt < N_ / 64; kt++) {
        const int j0 = kt * 64;

        // K tile [32][64] straight
        for (int i = tid; i < 512; i += 256) {
            int c = i >> 4, j4 = (i & 15) * 4;
            *(float4*)&Ks[c * 64 + j4] = *(const float4*)&Kb[(size_t)c * N_ + j0 + j4];
        }
        // V tile transposed to [j][c] with XOR swizzle (c ^ ((j>>3)&7)<<2)
        for (int i = tid; i < 4096; i += 256) {
            int c = i >> 4, j4 = (i & 15) * 4;
            float4 v4 = *(const float4*)&Vb[(size_t)c * N_ + j0 + j4];
            int xs = ((j4 >> 3) & 7) << 2;   // constant over the 4 j's (same 8-block)
            int cs = c ^ xs;
            Vs[(j4 + 0) * 256 + cs] = v4.x;
            Vs[(j4 + 1) * 256 + cs] = v4.y;
            Vs[(j4 + 2) * 256 + cs] = v4.z;
            Vs[(j4 + 3) * 256 + cs] = v4.w;
        }
        __syncthreads();

        // --- S = Q^T K (packed) ---
        u64_t s2[4][2];
#pragma unroll
        for (int i = 0; i < 4; i++) { s2[i][0] = pack2(0.f, 0.f); s2[i][1] = pack2(0.f, 0.f); }
#pragma unroll 8
        for (int c = 0; c < 32; c++) {
            float4 q4 = *(const float4*)&Qs[c * 64 + si0];
            float4 k4 = *(const float4*)&Ks[c * 64 + sj0];
            u64_t kp0 = pack2(k4.x, k4.y);
            u64_t kp1 = pack2(k4.z, k4.w);
            float qv[4] = {q4.x, q4.y, q4.z, q4.w};
#pragma unroll
            for (int i = 0; i < 4; i++) {
                u64_t qb = bcast2(qv[i]);
                s2[i][0] = fma2(kp0, qb, s2[i][0]);
                s2[i][1] = fma2(kp1, qb, s2[i][1]);
            }
        }
        float s[4][4];
#pragma unroll
        for (int i = 0; i < 4; i++) {
            float2 a = unpack2(s2[i][0]), bb2 = unpack2(s2[i][1]);
            s[i][0] = a.x; s[i][1] = a.y; s[i][2] = bb2.x; s[i][3] = bb2.y;
        }

        // --- online softmax: row max via shfl over the 16-lane row group ---
        float mx[4];
#pragma unroll
        for (int i = 0; i < 4; i++)
            mx[i] = fmaxf(fmaxf(s[i][0], s[i][1]), fmaxf(s[i][2], s[i][3]));
#pragma unroll
        for (int m = 1; m < 16; m <<= 1)
#pragma unroll
            for (int i = 0; i < 4; i++)
                mx[i] = fmaxf(mx[i], __shfl_xor_sync(0xffffffffu, mx[i], m));

        float mnew[4], al[4], rs[4];
#pragma unroll
        for (int i = 0; i < 4; i++) {
            float mo = smax[si0 + i];
            mnew[i] = fmaxf(mo, mx[i]);
            al[i]   = __expf(mo - mnew[i]);
            rs[i]   = 0.f;
        }

        // p = exp(s - mnew); store transposed+swizzled; accumulate row sums
        const int xs = ((sj0 >> 3) & 7) << 2;  // constant over jj (same 8-block)
        float p[4][4];
#pragma unroll
        for (int i = 0; i < 4; i++)
#pragma unroll
            for (int jj = 0; jj < 4; jj++) {
                p[i][jj] = __expf(s[i][jj] - mnew[i]);
                rs[i] += p[i][jj];
            }
#pragma unroll
        for (int jj = 0; jj < 4; jj++) {
            float4 p4 = make_float4(p[0][jj], p[1][jj], p[2][jj], p[3][jj]);
            *(float4*)&Ps[(sj0 + jj) * 64 + (si0 ^ xs)] = p4;
        }
#pragma unroll
        for (int m = 1; m < 16; m <<= 1)
#pragma unroll
            for (int i = 0; i < 4; i++)
                rs[i] += __shfl_xor_sync(0xffffffffu, rs[i], m);

        if ((tid & 15) == 0) {
#pragma unroll
            for (int i = 0; i < 4; i++) {
                smax[si0 + i]   = mnew[i];
                salpha[si0 + i] = al[i];
                ssum[si0 + i]   = ssum[si0 + i] * al[i] + rs[i];
            }
        }
        __syncthreads();

        // --- PV accumulate (packed), with alpha rescale ---
#pragma unroll
        for (int qq = 0; qq < 8; qq++) {
            u64_t ab = bcast2(salpha[q0t + qq]);
#pragma unroll
            for (int cc = 0; cc < 4; cc++)
                acc2[qq][cc] = mul2(acc2[qq][cc], ab);
        }

#pragma unroll 4
        for (int j = 0; j < 64; j++) {
            const int xj = ((j >> 3) & 7) << 2;
            float4 pa = *(const float4*)&Ps[j * 64  + (q0t ^ xj)];
            float4 pb = *(const float4*)&Ps[j * 64  + ((q0t + 4) ^ xj)];
            float4 va = *(const float4*)&Vs[j * 256 + (c0t ^ xj)];
            float4 vb = *(const float4*)&Vs[j * 256 + ((c0t + 4) ^ xj)];
            u64_t v2[4] = { pack2(va.x, va.y), pack2(va.z, va.w),
                            pack2(vb.x, vb.y), pack2(vb.z, vb.w) };
            float pv[8] = { pa.x, pa.y, pa.z, pa.w, pb.x, pb.y, pb.z, pb.w };
#pragma unroll
            for (int qq = 0; qq < 8; qq++) {
                u64_t pbb = bcast2(pv[qq]);
#pragma unroll
                for (int cc = 0; cc < 4; cc++)
                    acc2[qq][cc] = fma2(v2[cc], pbb, acc2[qq][cc]);
            }
        }
        __syncthreads();  // protect Ks/Vs/Ps/salpha for next tile
    }

    // Normalize and store
    float rl[8];
#pragma unroll
    for (int qq = 0; qq < 8; qq++) rl[qq] = 1.f / ssum[q0t + qq];

    float* Ob = O + (size_t)b * C_ * N_;
#pragma unroll
    for (int qq = 0; qq < 8; qq++) {
#pragma unroll
        for (int cc = 0; cc < 4; cc++) {
            float2 f = unpack2(acc2[qq][cc]);
            int c = c0t + cc * 2;
            Ob[(size_t)(c + 0) * N_ + q0 + q0t + qq] = f.x * rl[qq];
            Ob[(size_t)(c + 1) * N_ + q0 + q0t + qq] = f.y * rl[qq];
        }
    }
}

// ---------------------------------------------------------------------------
// kernel_launch
// Inputs (metadata order): x, Wq, bq, Wk, bk, Wv, bv, Wf, bf
// Output: float32 [B, C, H, W] = [8, 256, 64, 64]
// ---------------------------------------------------------------------------
extern "C" void kernel_launch(void* const* d_in, const int* in_sizes, int n_in,
                              void* d_out, int out_size)
{
    (void)in_sizes; (void)n_in; (void)out_size;
    const float* x  = (const float*)d_in[0];
    const float* Wq = (const float*)d_in[1];
    const float* bq = (const float*)d_in[2];
    const float* Wk = (const float*)d_in[3];
    const float* bk = (const float*)d_in[4];
    const float* Wv = (const float*)d_in[5];
    const float* bv = (const float*)d_in[6];
    const float* Wf = (const float*)d_in[7];
    const float* bf = (const float*)d_in[8];
    float* out = (float*)d_out;

    float *gq, *gk, *gv, *go;
    cudaGetSymbolAddress((void**)&gq, g_q);
    cudaGetSymbolAddress((void**)&gk, g_k);
    cudaGetSymbolAddress((void**)&gv, g_v);
    cudaGetSymbolAddress((void**)&go, g_o);

    cudaFuncSetAttribute(flash_kernel,
                         cudaFuncAttributeMaxDynamicSharedMemorySize,
                         FL_SMEM_BYTES);

    // Q, K projections: O=32
    proj_kernel<32><<<dim3(N_ / 64, 1, B_), 256>>>(Wq, bq, x, gq, CQK_);
    proj_kernel<32><<<dim3(N_ / 64, 1, B_), 256>>>(Wk, bk, x, gk, CQK_);
    // V projection: O=256
    proj_kernel<64><<<dim3(N_ / 64, C_ / 64, B_), 256>>>(Wv, bv, x, gv, C_);
    // Flash attention
    flash_kernel<<<dim3(N_ / 64, B_), 256, FL_SMEM_BYTES>>>(gq, gk, gv, go);
    // Final projection: O=256, input = attention output
    proj_kernel<64><<<dim3(N_ / 64, C_ / 64, B_), 256>>>(Wf, bf, go, out, C_);
}